// round 14
// baseline (speedup 1.0000x reference)
#include <cuda_runtime.h>
#include <cuda_bf16.h>

#define NB 16          // batch
#define NM 64          // gt boxes per image
#define A_TOTAL 48960
#define NK 9
#define JP 68          // padded j-stride (16B-aligned rows, conflict-free LDS.128)
#define XT 4
#define YT 8
#define NTHREADS (XT * YT * NK)   // 288

__global__ __launch_bounds__(NTHREADS, 7)
void anchors_assign_kernel(const float* __restrict__ gt_boxes,
                           const int*   __restrict__ gt_labels_raw,
                           float*       __restrict__ out)
{
    __shared__ __align__(16) float  s_IWn[XT * NK * JP];  // [x][k][jc]: clamp(IW)/AS
    __shared__ __align__(16) float  s_IH [YT * NK * JP];  // [y][k][jc]: clamp(IH)
    __shared__ __align__(16) float4 s_cbox[NM];           // compacted boxes (+pad)
    __shared__ float4 s_box0;                             // original box j=0
    __shared__ int    s_lab[NM];
    __shared__ int    s_cidx[NM];                         // compacted -> original j

    const int b   = blockIdx.y;
    const int tid = threadIdx.x;

    // ---- decode tile (heavy levels first): t = 169 - bx ----
    const int t = 169 - blockIdx.x;
    int x0, y0, base, W;
    float stride, bsize, rbsize;
    if (t < 128)      { x0 = (t & 15) * XT;          y0 = (t >> 4) * YT;       base = 0;     W = 64; stride = 8.f;  bsize = 32.f;  rbsize = 0.03125f;   }
    else if (t < 160) { int u = t - 128; x0 = (u & 7) * XT; y0 = (u >> 3) * YT; base = 36864; W = 32; stride = 16.f; bsize = 64.f;  rbsize = 0.015625f;  }
    else if (t < 168) { int u = t - 160; x0 = (u & 3) * XT; y0 = (u >> 2) * YT; base = 46080; W = 16; stride = 32.f; bsize = 128.f; rbsize = 0.0078125f; }
    else              { int u = t - 168; x0 = u * XT;       y0 = 0;            base = 48384; W = 8;  stride = 64.f; bsize = 256.f; rbsize = 0.00390625f;}

    // ---- phase 1: EVERY warp redundantly loads boxes, ballots, compacts. ----
    // All warps write identical values to shared (benign same-value races);
    // each warp's later reads are of its own writes -> no block barrier needed.
    // nc lands in registers of every thread via ballot.
    int nc;
    {
        const int lane = tid & 31;
        const float4* gb = (const float4*)(gt_boxes + (size_t)b * NM * 4);
        const float4 g0 = gb[lane];
        const float4 g1 = gb[lane + 32];

        // dtype probe: labels in [1,21); int64 layout has zero high words.
        const bool is64 = (gt_labels_raw[1] == 0) && (gt_labels_raw[3] == 0) &&
                          (gt_labels_raw[5] == 0);
        const int i0 = b * NM + lane;
        s_lab[lane]      = is64 ? gt_labels_raw[2 * i0]        : gt_labels_raw[i0];
        s_lab[lane + 32] = is64 ? gt_labels_raw[2 * (i0 + 32)] : gt_labels_raw[i0 + 32];

        // conservative overlap window: anchor centers +/- max half-extent
        const float ext   = 1.123f * bsize;   // >= 0.5*2^(2/3)*sqrt(2)*bsize
        const float txmin = (x0 + 0.5f) * stride - ext;
        const float txmax = (x0 + (XT - 0.5f)) * stride + ext;
        const float tymin = (y0 + 0.5f) * stride - ext;
        const float tymax = (y0 + (YT - 0.5f)) * stride + ext;
        const bool k0 = (g0.x < txmax) && (g0.z > txmin) && (g0.y < tymax) && (g0.w > tymin);
        const bool k1 = (g1.x < txmax) && (g1.z > txmin) && (g1.y < tymax) && (g1.w > tymin);
        const unsigned m0 = __ballot_sync(0xffffffffu, k0);
        const unsigned m1 = __ballot_sync(0xffffffffu, k1);
        const unsigned lt = (1u << lane) - 1u;
        nc = __popc(m0) + __popc(m1);
        if (k0) { int p = __popc(m0 & lt);               s_cbox[p] = g0; s_cidx[p] = lane; }
        if (k1) { int p = __popc(m0) + __popc(m1 & lt);  s_cbox[p] = g1; s_cidx[p] = lane + 32; }
        // pad [nc, nc4): degenerate zero-box -> overlap clamps to exactly 0
        if (lane < 4 && nc + lane < NM) s_cbox[nc + lane] = make_float4(0.f, 0.f, 0.f, 0.f);
        if (lane == 0) s_box0 = g0;
        __syncwarp();   // order this warp's smem writes before its phase-2 reads
    }
    const int nc4 = (nc + 3) & ~3;

    // ---- phase 2: build tables; 2 threads per row, 108 rows ----
    if (tid < 2 * (XT + YT) * NK) {                    // 216 threads
        const int r  = tid >> 1;                       // 0..107
        const int j0 = tid & 1;
        const bool isW = (r < XT * NK);
        const int rr = isW ? r : r - XT * NK;
        const int k  = rr % 9;
        const int c  = rr / 9;                         // x for IWn, y for IH
        const int kr = k / 3, ks = k % 3;
        const float sr  = (kr == 0) ? 0.70710678118654752f
                        : (kr == 1) ? 1.0f : 1.41421356237309505f;
        const float scl = (ks == 0) ? 1.0f
                        : (ks == 1) ? 1.2599210498948732f : 1.5874010519681994f;
        const float hw  = 0.5f * bsize * scl * sr;
        const float hh  = 0.5f * bsize * scl / sr;

        if (isW) {
            const float ctr = (x0 + c + 0.5f) * stride;
            const float lo = ctr - hw, hi = ctr + hw;
            const float area_a = 4.0f * hw * hh;
            float* __restrict__ row = s_IWn + rr * JP;
            for (int jc = j0; jc < nc4; jc += 2) {
                const float4 g  = s_cbox[jc];
                const float iw  = fminf(hi, g.z) - fmaxf(lo, g.x);
                const float ag  = (g.z - g.x) * (g.w - g.y);
                const float rAS = __fdividef(1.0f, area_a + ag);
                row[jc] = fmaxf(iw, 0.f) * rAS;
            }
        } else {
            const float ctr = (y0 + c + 0.5f) * stride;
            const float lo = ctr - hh, hi = ctr + hh;
            float* __restrict__ row = s_IH + rr * JP;
            for (int jc = j0; jc < nc4; jc += 2) {
                const float4 g = s_cbox[jc];
                const float ih = fminf(hi, g.w) - fmaxf(lo, g.y);
                row[jc] = fmaxf(ih, 0.f);
            }
        }
    }
    __syncthreads();                                   // the only block barrier

    // ---- main: dual-chain first-max argmax of s = IWn*IH (monotone in IoU) ----
    const int k  = tid % 9;
    const int xy = tid / 9;
    const int x  = xy & (XT - 1);
    const int y  = xy >> 2;

    const float* __restrict__ pw = s_IWn + (x * 9 + k) * JP;
    const float* __restrict__ ph = s_IH  + (y * 9 + k) * JP;

    float bsA = 0.0f, bsB = 0.0f;
    int   bcA = 0,    bcB = 0;
    #pragma unroll 2
    for (int j = 0; j < nc4; j += 4) {
        const float4 w = *(const float4*)(pw + j);
        const float4 h = *(const float4*)(ph + j);
        const float s0 = w.x * h.x;
        const float s1 = w.y * h.y;
        const float s2 = w.z * h.z;
        const float s3 = w.w * h.w;
        if (s0 > bsA) { bsA = s0; bcA = j;     }
        if (s1 > bsA) { bsA = s1; bcA = j + 1; }
        if (s2 > bsB) { bsB = s2; bcB = j + 2; }
        if (s3 > bsB) { bsB = s3; bcB = j + 3; }
    }
    // exact merge: strictly greater wins; on bit-equal scores the smaller
    // (earlier) index wins -> global first-max semantics preserved.
    float best_s; int bc;
    if (bsB > bsA || (bsB == bsA && bcB < bcA)) { best_s = bsB; bc = bcB; }
    else                                        { best_s = bsA; bc = bcA; }

    const bool hit   = (best_s > 0.0f);          // all-zero IoU -> reference j=0
    const int  jorig = hit ? s_cidx[bc] : 0;

    // ---- labels straight from s: iou = s/(1-s) monotone,
    // iou < 0.4 <=> s < 2/7 ; iou < 0.5 <=> s < 1/3 ----
    int lab = s_lab[jorig];
    if (best_s > 0.28571428571428571f && best_s < 0.33333333333333333f) lab = -1;
    if (best_s < 0.28571428571428571f)                                  lab = 0;

    // ---- deltas vs matched box (reciprocals from constants) ----
    const int kr = k / 3, ks = k % 3;
    const float sr      = (kr == 0) ? 0.70710678118654752f
                        : (kr == 1) ? 1.0f : 1.41421356237309505f;
    const float inv_sr  = (kr == 0) ? 1.41421356237309505f
                        : (kr == 1) ? 1.0f : 0.70710678118654752f;
    const float inv_scl = (ks == 0) ? 1.0f
                        : (ks == 1) ? 0.79370052598409974f : 0.62996052494743658f;
    const float raw = rbsize * inv_scl * inv_sr;   // 1/aw
    const float rah = rbsize * inv_scl * sr;       // 1/ah
    const float cx  = (x0 + x + 0.5f) * stride;
    const float cy  = (y0 + y + 0.5f) * stride;

    const float4 g  = hit ? s_cbox[bc] : s_box0;
    const float bw  = g.z - g.x;
    const float bh  = g.w - g.y;
    const float bcx = (g.x + g.z) * 0.5f;
    const float bcy = (g.y + g.w) * 0.5f;

    float4 d;
    d.x = (bcx - cx) * (10.0f * raw);
    d.y = (bcy - cy) * (10.0f * rah);
    d.z = __logf(bw * raw) * 5.0f;
    d.w = __logf(bh * rah) * 5.0f;

    // ---- stores: a consecutive in tid (k fastest) -> coalesced ----
    const int a = base + (((y0 + y) * W + (x0 + x)) * NK + k);
    ((float4*)out)[(size_t)b * A_TOTAL + a] = d;
    out[(size_t)NB * A_TOTAL * 4 + (size_t)b * A_TOTAL + a] = (float)lab;
}

extern "C" void kernel_launch(void* const* d_in, const int* in_sizes, int n_in,
                              void* d_out, int out_size)
{
    // inputs: f3, f4, f5, f6 (unused: shapes static), gt_boxes, gt_labels
    const float* gt_boxes  = (const float*)d_in[4];
    const int*   gt_labels = (const int*)d_in[5];
    float*       out       = (float*)d_out;

    dim3 block(NTHREADS);
    dim3 grid(170, NB);   // 128+32+8+2 tiles per batch, heavy-first via t remap
    anchors_assign_kernel<<<grid, block>>>(gt_boxes, gt_labels, out);
}

// round 15
// speedup vs baseline: 1.1366x; 1.1366x over previous
#include <cuda_runtime.h>
#include <cuda_bf16.h>

#define NB 16          // batch
#define NM 64          // gt boxes per image
#define A_TOTAL 48960
#define NK 9
#define JP 68          // padded j-stride (16B-aligned rows, conflict-free LDS.128)
#define XT 4
#define YT 8
#define NTHREADS (XT * YT * NK)   // 288

__global__ __launch_bounds__(NTHREADS, 7)
void anchors_assign_kernel(const float* __restrict__ gt_boxes,
                           const int*   __restrict__ gt_labels_raw,
                           float*       __restrict__ out)
{
    __shared__ __align__(16) float  s_IWn[XT * NK * JP];  // [x][k][jc]: clamp(IW)/AS
    __shared__ __align__(16) float  s_IH [YT * NK * JP];  // [y][k][jc]: clamp(IH)
    __shared__ __align__(16) float4 s_cbox[NM];           // compacted boxes (+pad)
    __shared__ float4 s_box0;                             // original box j=0
    __shared__ int    s_lab[NM];
    __shared__ int    s_cidx[NM];                         // compacted -> original j
    __shared__ int    s_nc;

    const int b   = blockIdx.y;
    const int tid = threadIdx.x;

    // ---- decode tile (heavy levels first): t = 169 - bx ----
    const int t = 169 - blockIdx.x;
    int x0, y0, base, W;
    float stride, bsize, rbsize;
    if (t < 128)      { x0 = (t & 15) * XT;          y0 = (t >> 4) * YT;       base = 0;     W = 64; stride = 8.f;  bsize = 32.f;  rbsize = 0.03125f;   }
    else if (t < 160) { int u = t - 128; x0 = (u & 7) * XT; y0 = (u >> 3) * YT; base = 36864; W = 32; stride = 16.f; bsize = 64.f;  rbsize = 0.015625f;  }
    else if (t < 168) { int u = t - 160; x0 = (u & 3) * XT; y0 = (u >> 2) * YT; base = 46080; W = 16; stride = 32.f; bsize = 128.f; rbsize = 0.0078125f; }
    else              { int u = t - 168; x0 = u * XT;       y0 = 0;            base = 48384; W = 8;  stride = 64.f; bsize = 256.f; rbsize = 0.00390625f;}

    // ---- phase 1 (warp 0 only): load, window-test, stable compaction ----
    if (tid < 32) {
        const int lane = tid;
        const float4* gb = (const float4*)(gt_boxes + (size_t)b * NM * 4);
        const float4 g0 = gb[lane];
        const float4 g1 = gb[lane + 32];

        // dtype probe: labels in [1,21); int64 layout has zero high words.
        const bool is64 = (gt_labels_raw[1] == 0) && (gt_labels_raw[3] == 0) &&
                          (gt_labels_raw[5] == 0);
        const int i0 = b * NM + lane;
        s_lab[lane]      = is64 ? gt_labels_raw[2 * i0]        : gt_labels_raw[i0];
        s_lab[lane + 32] = is64 ? gt_labels_raw[2 * (i0 + 32)] : gt_labels_raw[i0 + 32];

        // conservative overlap window: anchor centers +/- max half-extent
        const float ext   = 1.123f * bsize;   // >= 0.5*2^(2/3)*sqrt(2)*bsize
        const float txmin = (x0 + 0.5f) * stride - ext;
        const float txmax = (x0 + (XT - 0.5f)) * stride + ext;
        const float tymin = (y0 + 0.5f) * stride - ext;
        const float tymax = (y0 + (YT - 0.5f)) * stride + ext;
        const bool k0 = (g0.x < txmax) && (g0.z > txmin) && (g0.y < tymax) && (g0.w > tymin);
        const bool k1 = (g1.x < txmax) && (g1.z > txmin) && (g1.y < tymax) && (g1.w > tymin);
        const unsigned m0 = __ballot_sync(0xffffffffu, k0);
        const unsigned m1 = __ballot_sync(0xffffffffu, k1);
        const unsigned lt = (1u << lane) - 1u;
        const int nc = __popc(m0) + __popc(m1);
        if (k0) { int p = __popc(m0 & lt);               s_cbox[p] = g0; s_cidx[p] = lane; }
        if (k1) { int p = __popc(m0) + __popc(m1 & lt);  s_cbox[p] = g1; s_cidx[p] = lane + 32; }
        // pad [nc, nc4): degenerate zero-box -> overlap clamps to exactly 0
        if (lane < 4 && nc + lane < NM) s_cbox[nc + lane] = make_float4(0.f, 0.f, 0.f, 0.f);
        if (lane == 0) { s_nc = nc; s_box0 = g0; }
    }
    __syncthreads();                                   // barrier #1

    const int nc  = s_nc;
    const int nc4 = (nc + 3) & ~3;

    // ---- phase 2: build tables, one thread per (k, jc) pair ----
    // Each pair loads its box ONCE, computes rAS ONCE, emits 4 IW + 8 IH
    // entries. Consecutive tid -> consecutive jc in the same row: STS
    // conflict-free; cbox LDS.128 consecutive.
    for (int p = tid; p < NK * nc4; p += NTHREADS) {
        const int jc = p % 64;          // nc4 <= 64; use mod-64 split to keep
        const int k  = p / 64 + ((jc >= nc4) ? 0 : 0); // (placeholder, fixed below)
        (void)k;
        break;                           // structured version below
    }
    {
        const int total = NK * nc4;
        for (int p = tid; p < total; p += NTHREADS) {
            // jc fastest within a k: p = k*nc4 + jc
            int k  = p / nc4;
            int jc = p - k * nc4;
            const int kr = k / 3, ks = k - kr * 3;
            const float sr  = (kr == 0) ? 0.70710678118654752f
                            : (kr == 1) ? 1.0f : 1.41421356237309505f;
            const float scl = (ks == 0) ? 1.0f
                            : (ks == 1) ? 1.2599210498948732f : 1.5874010519681994f;
            const float hw  = 0.5f * bsize * scl * sr;
            const float hh  = 0.5f * bsize * scl / sr;

            const float4 g  = s_cbox[jc];
            const float ag  = (g.z - g.x) * (g.w - g.y);
            const float rAS = __fdividef(1.0f, 4.0f * hw * hh + ag);

            float* __restrict__ wcol = s_IWn + k * JP + jc;
            #pragma unroll
            for (int xx = 0; xx < XT; ++xx) {
                const float c = (x0 + xx + 0.5f) * stride;
                const float iw = fminf(c + hw, g.z) - fmaxf(c - hw, g.x);
                wcol[xx * (NK * JP)] = fmaxf(iw, 0.f) * rAS;
            }
            float* __restrict__ hcol = s_IH + k * JP + jc;
            #pragma unroll
            for (int yy = 0; yy < YT; ++yy) {
                const float c = (y0 + yy + 0.5f) * stride;
                const float ih = fminf(c + hh, g.w) - fmaxf(c - hh, g.y);
                hcol[yy * (NK * JP)] = fmaxf(ih, 0.f);
            }
        }
    }
    __syncthreads();                                   // barrier #2

    // ---- main: dual-chain first-max argmax of s = IWn*IH (monotone in IoU) ----
    const int k  = tid % 9;
    const int xy = tid / 9;
    const int x  = xy & (XT - 1);
    const int y  = xy >> 2;

    const float* __restrict__ pw = s_IWn + (x * 9 + k) * JP;
    const float* __restrict__ ph = s_IH  + (y * 9 + k) * JP;

    float bsA = 0.0f, bsB = 0.0f;
    int   bcA = 0,    bcB = 0;
    #pragma unroll 2
    for (int j = 0; j < nc4; j += 4) {
        const float4 w = *(const float4*)(pw + j);
        const float4 h = *(const float4*)(ph + j);
        const float s0 = w.x * h.x;
        const float s1 = w.y * h.y;
        const float s2 = w.z * h.z;
        const float s3 = w.w * h.w;
        if (s0 > bsA) { bsA = s0; bcA = j;     }
        if (s1 > bsA) { bsA = s1; bcA = j + 1; }
        if (s2 > bsB) { bsB = s2; bcB = j + 2; }
        if (s3 > bsB) { bsB = s3; bcB = j + 3; }
    }
    // exact merge: strictly greater wins; on bit-equal scores the smaller
    // (earlier) index wins -> global first-max semantics preserved.
    float best_s; int bc;
    if (bsB > bsA || (bsB == bsA && bcB < bcA)) { best_s = bsB; bc = bcB; }
    else                                        { best_s = bsA; bc = bcA; }

    const bool hit   = (best_s > 0.0f);          // all-zero IoU -> reference j=0
    const int  jorig = hit ? s_cidx[bc] : 0;

    // ---- labels straight from s: iou = s/(1-s) monotone,
    // iou < 0.4 <=> s < 2/7 ; iou < 0.5 <=> s < 1/3 ----
    int lab = s_lab[jorig];
    if (best_s > 0.28571428571428571f && best_s < 0.33333333333333333f) lab = -1;
    if (best_s < 0.28571428571428571f)                                  lab = 0;

    // ---- deltas vs matched box (reciprocals from constants) ----
    const int kr = k / 3, ks = k % 3;
    const float sr      = (kr == 0) ? 0.70710678118654752f
                        : (kr == 1) ? 1.0f : 1.41421356237309505f;
    const float inv_sr  = (kr == 0) ? 1.41421356237309505f
                        : (kr == 1) ? 1.0f : 0.70710678118654752f;
    const float inv_scl = (ks == 0) ? 1.0f
                        : (ks == 1) ? 0.79370052598409974f : 0.62996052494743658f;
    const float raw = rbsize * inv_scl * inv_sr;   // 1/aw
    const float rah = rbsize * inv_scl * sr;       // 1/ah
    const float cx  = (x0 + x + 0.5f) * stride;
    const float cy  = (y0 + y + 0.5f) * stride;

    const float4 g  = hit ? s_cbox[bc] : s_box0;
    const float bw  = g.z - g.x;
    const float bh  = g.w - g.y;
    const float bcx = (g.x + g.z) * 0.5f;
    const float bcy = (g.y + g.w) * 0.5f;

    float4 d;
    d.x = (bcx - cx) * (10.0f * raw);
    d.y = (bcy - cy) * (10.0f * rah);
    d.z = __logf(bw * raw) * 5.0f;
    d.w = __logf(bh * rah) * 5.0f;

    // ---- stores: a consecutive in tid (k fastest) -> coalesced ----
    const int a = base + (((y0 + y) * W + (x0 + x)) * NK + k);
    ((float4*)out)[(size_t)b * A_TOTAL + a] = d;
    out[(size_t)NB * A_TOTAL * 4 + (size_t)b * A_TOTAL + a] = (float)lab;
}

extern "C" void kernel_launch(void* const* d_in, const int* in_sizes, int n_in,
                              void* d_out, int out_size)
{
    // inputs: f3, f4, f5, f6 (unused: shapes static), gt_boxes, gt_labels
    const float* gt_boxes  = (const float*)d_in[4];
    const int*   gt_labels = (const int*)d_in[5];
    float*       out       = (float*)d_out;

    dim3 block(NTHREADS);
    dim3 grid(170, NB);   // 128+32+8+2 tiles per batch, heavy-first via t remap
    anchors_assign_kernel<<<grid, block>>>(gt_boxes, gt_labels, out);
}